// round 17
// baseline (speedup 1.0000x reference)
#include <cuda_runtime.h>
#include <cuda_bf16.h>
#include <cstdint>
#include <math.h>

#define DEV_INLINE __device__ __forceinline__

// ---------------- problem constants ----------------
static constexpr int D_DIM = 512;
static constexpr int MAXB  = 2048;
static constexpr int MAXV  = 32000;
static constexpr float S_SCALE = 30.0f;
static constexpr float LOG2E   = 1.4426950408889634f;
static constexpr float S_LOG2E = S_SCALE * LOG2E;            // 43.2808...
static constexpr float COS_M = 0.8775825618903728f;          // cos(0.5)
static constexpr float SIN_M = 0.4794255386042030f;          // sin(0.5)

// ---------------- scratch (device globals; no cudaMalloc allowed) ----------------
__device__ __nv_bfloat16 g_nx[MAXB * D_DIM];
__device__ __nv_bfloat16 g_nW[MAXV * D_DIM];
__device__ float g_rowsum[MAXB];
__device__ float g_cosy[MAXB];
__device__ unsigned g_done;

// ---------------- PTX helpers (plain sm_103 ISA only) --------
DEV_INLINE uint32_t smem_u32(const void* p) {
    uint32_t a;
    asm("{ .reg .u64 t; cvta.to.shared.u64 t, %1; cvt.u32.u64 %0, t; }"
        : "=r"(a) : "l"(p));
    return a;
}

DEV_INLINE float ex2_fast(float x) {     // single MUFU.EX2
    float y;
    asm("ex2.approx.ftz.f32 %0, %1;" : "=f"(y) : "f"(x));
    return y;
}

DEV_INLINE void cp_async16(uint32_t saddr, const void* gptr) {
    asm volatile("cp.async.cg.shared.global [%0], [%1], 16;"
                 :: "r"(saddr), "l"(gptr) : "memory");
}
DEV_INLINE void cp_commit() { asm volatile("cp.async.commit_group;" ::: "memory"); }
template <int N>
DEV_INLINE void cp_wait() { asm volatile("cp.async.wait_group %0;" :: "n"(N) : "memory"); }

DEV_INLINE void ldsm_x4(uint32_t& r0, uint32_t& r1, uint32_t& r2, uint32_t& r3,
                        uint32_t addr) {
    asm volatile("ldmatrix.sync.aligned.m8n8.x4.shared.b16 {%0,%1,%2,%3}, [%4];"
                 : "=r"(r0), "=r"(r1), "=r"(r2), "=r"(r3) : "r"(addr));
}

DEV_INLINE void mma16816(float* c, const uint32_t* a, const uint32_t* b) {
    asm volatile(
        "mma.sync.aligned.m16n8k16.row.col.f32.bf16.bf16.f32 "
        "{%0,%1,%2,%3}, {%4,%5,%6,%7}, {%8,%9}, {%0,%1,%2,%3};"
        : "+f"(c[0]), "+f"(c[1]), "+f"(c[2]), "+f"(c[3])
        : "r"(a[0]), "r"(a[1]), "r"(a[2]), "r"(a[3]), "r"(b[0]), "r"(b[1]));
}

// ---------------- kernel 1: normalize (warp/row) + label-cos warps ----------
// Warps [0, B+V): normalize one row (shuffle reduce, no smem/barriers).
// Warps [B+V, B+V+B): exact fp32 cos at the label column.
__global__ void normalize_kernel(const float* __restrict__ x,
                                 const float* __restrict__ W,
                                 __nv_bfloat16* __restrict__ nx,
                                 __nv_bfloat16* __restrict__ nW,
                                 float* __restrict__ rowsum,
                                 float* __restrict__ cosy,
                                 const void* __restrict__ labels,
                                 int B, int V) {
    int gw = (int)((blockIdx.x * blockDim.x + threadIdx.x) >> 5);
    int lane = threadIdx.x & 31;
    int total = B + V;

    if (gw >= total) {                           // label-cos warp
        int b = gw - total;
        if (b >= B) return;
        const int* l32 = (const int*)labels;
        int vv = l32[2 * lane + 1];
        unsigned m = __ballot_sync(0xFFFFFFFFu, vv == 0);
        bool lab64 = (m == 0xFFFFFFFFu);
        long long y = lab64 ? ((const long long*)labels)[b]
                            : (long long)l32[b];
        if (b == 0 && lane == 0) g_done = 0u;    // reset GEMM arrival counter
        const float* xr = x + (size_t)b * D_DIM;
        const float* wr = W + (size_t)y * D_DIM;
        float dot = 0.f, xx = 0.f, ww = 0.f;
        #pragma unroll
        for (int i = 0; i < 4; i++) {
            int k = (lane + i * 32) * 4;
            float4 a = *(const float4*)(xr + k);
            float4 bb = *(const float4*)(wr + k);
            dot += a.x * bb.x + a.y * bb.y + a.z * bb.z + a.w * bb.w;
            xx  += a.x * a.x + a.y * a.y + a.z * a.z + a.w * a.w;
            ww  += bb.x * bb.x + bb.y * bb.y + bb.z * bb.z + bb.w * bb.w;
        }
        #pragma unroll
        for (int o = 16; o; o >>= 1) {
            dot += __shfl_xor_sync(0xFFFFFFFFu, dot, o);
            xx  += __shfl_xor_sync(0xFFFFFFFFu, xx, o);
            ww  += __shfl_xor_sync(0xFFFFFFFFu, ww, o);
        }
        if (lane == 0)
            cosy[b] = dot / (fmaxf(sqrtf(xx), 1e-12f) * fmaxf(sqrtf(ww), 1e-12f));
        return;
    }

    const float* in;
    __nv_bfloat16* outp;
    int r;
    if (gw < B) { in = x; outp = nx; r = gw; }
    else        { in = W; outp = nW; r = gw - B; }

    float4 v[4];
    float ss = 0.f;
    #pragma unroll
    for (int i = 0; i < 4; i++) {
        v[i] = *(const float4*)(in + (size_t)r * D_DIM + (lane + i * 32) * 4);
        ss += v[i].x * v[i].x + v[i].y * v[i].y + v[i].z * v[i].z + v[i].w * v[i].w;
    }
    #pragma unroll
    for (int o = 16; o; o >>= 1) ss += __shfl_xor_sync(0xFFFFFFFFu, ss, o);
    float inv = 1.0f / fmaxf(sqrtf(ss), 1e-12f);
    #pragma unroll
    for (int i = 0; i < 4; i++) {
        __nv_bfloat162 h0 = __floats2bfloat162_rn(v[i].x * inv, v[i].y * inv);
        __nv_bfloat162 h1 = __floats2bfloat162_rn(v[i].z * inv, v[i].w * inv);
        uint2 pk;
        pk.x = *(uint32_t*)&h0;
        pk.y = *(uint32_t*)&h1;
        *(uint2*)(outp + (size_t)r * D_DIM + (lane + i * 32) * 4) = pk;
    }
    if (gw < B && lane == 0) rowsum[gw] = 0.0f;
}

// ---------------- kernel 2: A-resident HMMA GEMM + fused finalize ----------
static constexpr int TM = 128;
static constexpr int TN = 128;
static constexpr int KC = 64;
static constexpr int KT = D_DIM / KC;          // 8
static constexpr int BSTAGES = 4;
static constexpr int NTHR = 256;
static constexpr int NGROUP = 9;               // 9*16 = 144 CTAs
static constexpr int A_BYTES = TM * D_DIM * 2;          // 131072
static constexpr int B_STAGE_BYTES = TN * KC * 2;       // 16384
static constexpr int SM_TOTAL = A_BYTES + BSTAGES * B_STAGE_BYTES;  // 196608

DEV_INLINE uint32_t a_off(int row, int k) {
    return (uint32_t)(row * 1024 + (((k >> 3) ^ (row & 7)) << 4) + ((k & 7) << 1));
}
DEV_INLINE uint32_t sw_off(int row, int k) {
    return (uint32_t)(row * 128 + (((k >> 3) ^ (row & 7)) << 4) + ((k & 7) << 1));
}

DEV_INLINE void load_b(uint32_t sbase, const __nv_bfloat16* __restrict__ src,
                       int n0, int k0, int tid) {
    #pragma unroll
    for (int i = 0; i < TN * 8 / NTHR; i++) {      // 4 iters
        int idx = i * NTHR + tid;
        int row = idx >> 3;
        int kc  = (idx & 7) << 3;
        cp_async16(sbase + sw_off(row, kc),
                   src + (size_t)(n0 + row) * D_DIM + k0 + kc);
    }
}

__global__ void __launch_bounds__(NTHR, 1)
gemm_expsum_kernel(const __nv_bfloat16* __restrict__ A,
                   const __nv_bfloat16* __restrict__ Bm,
                   float* __restrict__ rowsum,
                   const float* __restrict__ cosy,
                   float* __restrict__ out, int nvt, int B) {
    extern __shared__ char smem[];
    const uint32_t sa = smem_u32(smem);                 // A region
    const uint32_t sbB = sa + A_BYTES;                  // B ring base
    const int tid = threadIdx.x;
    const int wid = tid >> 5, lid = tid & 31;
    const int wm = wid & 1;          // 0..1 (M, 64 rows)
    const int wn = wid >> 1;         // 0..3 (N, 32 cols)
    const int m0 = blockIdx.y * TM;

    const int t0 = (blockIdx.x * nvt) / NGROUP;
    const int t1 = ((blockIdx.x + 1) * nvt) / NGROUP;

    if (t0 < t1) {
        // ---- load A tile once (128KB) ----
        #pragma unroll
        for (int i = 0; i < TM * 64 / NTHR; i++) {          // 32 iters
            int idx = i * NTHR + tid;
            int row = idx >> 6;
            int c   = idx & 63;
            cp_async16(sa + a_off(row, c * 8),
                       A + (size_t)(m0 + row) * D_DIM + c * 8);
        }
        cp_commit();

        // ---- B prologue: chunks 0,1,2 of first tile ----
        int n0 = t0 * TN;
        #pragma unroll
        for (int s = 0; s < BSTAGES - 1; s++) {
            load_b(sbB + s * B_STAGE_BYTES, Bm, n0, s * KC, tid);
            cp_commit();
        }

        const int a_row = wm * 64 + (lid & 15);
        const int a_kc  = (lid >> 4) << 3;
        const int b_row = wn * 32 + (lid & 15);
        const int b_kc  = (lid >> 4) << 3;

        float acc[4][4][4];
        #pragma unroll
        for (int i = 0; i < 4; i++)
            #pragma unroll
            for (int j = 0; j < 4; j++)
                #pragma unroll
                for (int q = 0; q < 4; q++) acc[i][j][q] = 0.f;

        int slot = 0;
        for (int t = t0; t < t1; t++) {
            const int nn0 = (t + 1 < t1) ? (t + 1) * TN : -1;
            #pragma unroll
            for (int kt = 0; kt < KT; kt++) {
                cp_wait<BSTAGES - 2>();
                __syncthreads();

                int ps = (slot + BSTAGES - 1) & (BSTAGES - 1);
                if (kt + BSTAGES - 1 < KT) {
                    load_b(sbB + ps * B_STAGE_BYTES, Bm, n0, (kt + BSTAGES - 1) * KC, tid);
                } else if (nn0 >= 0) {
                    load_b(sbB + ps * B_STAGE_BYTES, Bm, nn0, (kt + BSTAGES - 1 - KT) * KC, tid);
                }
                cp_commit();

                const uint32_t sbm = sbB + slot * B_STAGE_BYTES;
                const int kbase = kt * KC;

                #pragma unroll
                for (int ks = 0; ks < KC / 16; ks++) {
                    uint32_t afr[4][4];
                    #pragma unroll
                    for (int mt = 0; mt < 4; mt++)
                        ldsm_x4(afr[mt][0], afr[mt][1], afr[mt][2], afr[mt][3],
                                sa + a_off(a_row + mt * 16, kbase + ks * 16 + a_kc));
                    uint32_t bfr[2][4];
                    #pragma unroll
                    for (int np = 0; np < 2; np++)
                        ldsm_x4(bfr[np][0], bfr[np][1], bfr[np][2], bfr[np][3],
                                sbm + sw_off(b_row + np * 16, ks * 16 + b_kc));
                    #pragma unroll
                    for (int mt = 0; mt < 4; mt++)
                        #pragma unroll
                        for (int nt = 0; nt < 4; nt++)
                            mma16816(acc[mt][nt], afr[mt], &bfr[nt >> 1][(nt & 1) * 2]);
                }
                slot = (slot + 1) & (BSTAGES - 1);
            }

            #pragma unroll
            for (int mt = 0; mt < 4; mt++) {
                float s0 = 0.f, s1 = 0.f;
                #pragma unroll
                for (int nt = 0; nt < 4; nt++) {
                    s0 += ex2_fast(acc[mt][nt][0] * S_LOG2E)
                        + ex2_fast(acc[mt][nt][1] * S_LOG2E);
                    s1 += ex2_fast(acc[mt][nt][2] * S_LOG2E)
                        + ex2_fast(acc[mt][nt][3] * S_LOG2E);
                    #pragma unroll
                    for (int q = 0; q < 4; q++) acc[mt][nt][q] = 0.f;
                }
                s0 += __shfl_xor_sync(0xFFFFFFFFu, s0, 1);
                s0 += __shfl_xor_sync(0xFFFFFFFFu, s0, 2);
                s1 += __shfl_xor_sync(0xFFFFFFFFu, s1, 1);
                s1 += __shfl_xor_sync(0xFFFFFFFFu, s1, 2);
                if ((lid & 3) == 0) {
                    int r = m0 + wm * 64 + mt * 16 + (lid >> 2);
                    atomicAdd(&rowsum[r], s0);
                    atomicAdd(&rowsum[r + 8], s1);
                }
            }
            n0 = nn0;
        }
    }

    // ---- fused finalize: last-arriving CTA reduces the loss ----
    __shared__ unsigned s_last;
    __shared__ float red[NTHR / 32];
    __syncthreads();
    if (tid == 0) {
        __threadfence();
        unsigned v = atomicAdd(&g_done, 1u);
        s_last = (v == (unsigned)(NGROUP * gridDim.y) - 1u) ? 1u : 0u;
    }
    __syncthreads();
    if (s_last) {
        float local = 0.f;
        for (int b = tid; b < B; b += NTHR) {
            float c  = fminf(fmaxf(cosy[b], -1.f), 1.f);
            float sn = sqrtf(fmaxf(1.f - c * c, 0.f));
            float phi = c * COS_M - sn * SIN_M;
            float S = rowsum[b] - exp2f(S_LOG2E * c) + exp2f(S_LOG2E * phi);
            local += logf(S) - S_SCALE * phi;
        }
        #pragma unroll
        for (int o = 16; o; o >>= 1) local += __shfl_xor_sync(0xFFFFFFFFu, local, o);
        if (lid == 0) red[wid] = local;
        __syncthreads();
        if (tid == 0) {
            float s = 0.f;
            #pragma unroll
            for (int i = 0; i < NTHR / 32; i++) s += red[i];
            out[0] = s / (float)B;
        }
    }
}

// ---------------- launch ----------------
extern "C" void kernel_launch(void* const* d_in, const int* in_sizes, int n_in,
                              void* d_out, int out_size) {
    const float* x = (const float*)d_in[0];
    const float* W = (const float*)d_in[1];
    const void*  labels = d_in[2];
    float* out = (float*)d_out;

    int B = in_sizes[0] / D_DIM;
    int V = in_sizes[1] / D_DIM;
    int nvt = V / TN;                           // 250

    __nv_bfloat16 *nx, *nW;
    float *rowsum, *cosy;
    cudaGetSymbolAddress((void**)&nx, g_nx);
    cudaGetSymbolAddress((void**)&nW, g_nW);
    cudaGetSymbolAddress((void**)&rowsum, g_rowsum);
    cudaGetSymbolAddress((void**)&cosy, g_cosy);

    cudaFuncSetAttribute(gemm_expsum_kernel,
                         cudaFuncAttributeMaxDynamicSharedMemorySize, SM_TOTAL);

    int nwarps = B + V + B;                     // normalize + cosy warps
    int nblocks = (nwarps * 32 + 255) / 256;
    normalize_kernel<<<nblocks, 256>>>(x, W, nx, nW, rowsum, cosy, labels, B, V);
    gemm_expsum_kernel<<<dim3(NGROUP, B / TM), NTHR, SM_TOTAL>>>(nx, nW, rowsum,
                                                                 cosy, out, nvt, B);
}